// round 4
// baseline (speedup 1.0000x reference)
#include <cuda_runtime.h>
#include <cuda_bf16.h>

// DCN cross network, fused over L=4 layers.
// x: (16384, 1024) fp32; weights/biases: (4, 1024).
// x_{l+1} = x0 * (x_l . w_l) + b_l + x_l
//
// R3: the R2 kernel was MIO/issue-bound (L1 66%, DRAM 29%): 8 warps/row each
// paying 20 SHFL + 8 LDS + 4 BAR of reduction overhead. Now:
//  - 128 threads x 8 elems/thread: reduction overhead amortized 2x, cross-warp
//    sum is one broadcast LDS.128 (4 partials).
//  - packed f32x2 FMA/ADD (sm_100a): dot 8->5 issues, epilogue 16->8 issues.
//  - W/B register-resident; next-row x prefetched (MLP=2/warp).

#define B_ROWS   16384
#define L_LAYERS 4
#define THREADS  128
#define R_ROWS   8          // grid = 2048
#define VPR      256        // 16B vectors per row (1024 floats)

typedef unsigned long long u64;

__device__ __forceinline__ u64 fma2(u64 a, u64 b, u64 c) {
    u64 d; asm("fma.rn.f32x2 %0, %1, %2, %3;" : "=l"(d) : "l"(a), "l"(b), "l"(c)); return d;
}
__device__ __forceinline__ u64 add2(u64 a, u64 b) {
    u64 d; asm("add.rn.f32x2 %0, %1, %2;" : "=l"(d) : "l"(a), "l"(b)); return d;
}
__device__ __forceinline__ u64 mul2(u64 a, u64 b) {
    u64 d; asm("mul.rn.f32x2 %0, %1, %2;" : "=l"(d) : "l"(a), "l"(b)); return d;
}
__device__ __forceinline__ float hsum2(u64 p) {
    float lo, hi; asm("mov.b64 {%0, %1}, %2;" : "=f"(lo), "=f"(hi) : "l"(p)); return lo + hi;
}
__device__ __forceinline__ u64 pack2(float s) {
    u64 d; asm("mov.b64 %0, {%1, %1};" : "=l"(d) : "f"(s)); return d;
}

__global__ __launch_bounds__(THREADS, 4)
void dcn_cross_kernel(const ulonglong2* __restrict__ x,
                      const ulonglong2* __restrict__ w,
                      const ulonglong2* __restrict__ b,
                      ulonglong2* __restrict__ out) {
    const int t    = threadIdx.x;      // 0..127
    const int lane = t & 31;
    const int wid  = t >> 5;           // 0..3

    __shared__ __align__(16) float s_warp[L_LAYERS][4];

    // W/B register-resident for the CTA lifetime (packed f32x2 pairs)
    ulonglong2 W[L_LAYERS][2], Bv[L_LAYERS][2];
    #pragma unroll
    for (int l = 0; l < L_LAYERS; l++) {
        W[l][0]  = w[l * VPR + t];
        W[l][1]  = w[l * VPR + t + THREADS];
        Bv[l][0] = b[l * VPR + t];
        Bv[l][1] = b[l * VPR + t + THREADS];
    }

    const size_t base = (size_t)blockIdx.x * (R_ROWS * VPR) + t;

    ulonglong2 xin0 = x[base];                 // prefetch row 0
    ulonglong2 xin1 = x[base + THREADS];

    #pragma unroll 1
    for (int r = 0; r < R_ROWS; r++) {
        const ulonglong2 x00 = xin0, x01 = xin1;
        if (r + 1 < R_ROWS) {                  // prefetch next row
            xin0 = x[base + (size_t)(r + 1) * VPR];
            xin1 = x[base + (size_t)(r + 1) * VPR + THREADS];
        }
        ulonglong2 xc0 = x00, xc1 = x01;

        #pragma unroll
        for (int l = 0; l < L_LAYERS; l++) {
            // packed partial dot over this thread's 8 elements
            u64 p2 = mul2(xc0.x, W[l][0].x);
            p2 = fma2(xc0.y, W[l][0].y, p2);
            p2 = fma2(xc1.x, W[l][1].x, p2);
            p2 = fma2(xc1.y, W[l][1].y, p2);
            float p = hsum2(p2);

            // warp reduce
            #pragma unroll
            for (int o = 16; o > 0; o >>= 1)
                p += __shfl_down_sync(0xffffffffu, p, o);
            if (lane == 0) s_warp[l][wid] = p;
            __syncthreads();

            // cross-warp: one broadcast LDS.128 + 3 adds
            const float4 sv = *reinterpret_cast<const float4*>(s_warp[l]);
            const u64 s2 = pack2((sv.x + sv.y) + (sv.z + sv.w));

            // packed epilogue: xc = x0*s + (b + xc)
            xc0.x = fma2(x00.x, s2, add2(Bv[l][0].x, xc0.x));
            xc0.y = fma2(x00.y, s2, add2(Bv[l][0].y, xc0.y));
            xc1.x = fma2(x01.x, s2, add2(Bv[l][1].x, xc1.x));
            xc1.y = fma2(x01.y, s2, add2(Bv[l][1].y, xc1.y));
        }

        out[base + (size_t)r * VPR]           = xc0;
        out[base + (size_t)r * VPR + THREADS] = xc1;
    }
}

extern "C" void kernel_launch(void* const* d_in, const int* in_sizes, int n_in,
                              void* d_out, int out_size) {
    const ulonglong2* x = (const ulonglong2*)d_in[0];
    const ulonglong2* w = (const ulonglong2*)d_in[1];
    const ulonglong2* b = (const ulonglong2*)d_in[2];
    ulonglong2* o = (ulonglong2*)d_out;
    dcn_cross_kernel<<<B_ROWS / R_ROWS, THREADS>>>(x, w, b, o);
}

// round 6
// speedup vs baseline: 1.1044x; 1.1044x over previous
#include <cuda_runtime.h>
#include <cuda_bf16.h>

// DCN cross network, fused over L=4 layers — affine-span reformulation.
// x_{l+1} = x0*(x_l.w_l) + b_l + x_l  keeps x_l = gamma_l*x0 + B_l with
// B_l = sum_{j<l} b_j row-independent. So:
//   t_l   = x0 . w_l            (4 independent dots, ONE reduction pass)
//   beta_l= B_l . w_l           (row-independent scalar, computed per CTA)
//   s_l   = gamma_l*t_l + beta_l;  gamma_{l+1} = gamma_l + s_l
//   out   = gamma_4 * x0 + (b0+b1+b2+b3)
// Per row: 1 load, 1 reduction phase, 1 barrier, 1 store. No per-layer
// vector work at all. Two rows in flight per iteration for ILP.

#define B_ROWS   16384
#define L_LAYERS 4
#define THREADS  256
#define VPR      256        // float4 vectors per row
#define R_PAIRS  4          // 8 rows per CTA -> grid = 2048

__device__ __forceinline__ float dot4(const float4 a, const float4 b) {
    return a.x * b.x + a.y * b.y + a.z * b.z + a.w * b.w;
}
__device__ __forceinline__ float4 add4(const float4 a, const float4 b) {
    return make_float4(a.x + b.x, a.y + b.y, a.z + b.z, a.w + b.w);
}

__global__ __launch_bounds__(THREADS, 4)
void dcn_cross_kernel(const float4* __restrict__ x,
                      const float4* __restrict__ w,
                      const float4* __restrict__ b,
                      float4* __restrict__ out) {
    const int t    = threadIdx.x;      // 0..255
    const int lane = t & 31;
    const int wid  = t >> 5;           // 0..7

    __shared__ __align__(16) float4 sred[2][2][8];  // [parity][rowInPair][warp]
    __shared__ __align__(16) float4 sbeta[8];

    // ---- prologue: W register-resident, Bsum slice, beta partials ----
    float4 W[L_LAYERS];
    #pragma unroll
    for (int l = 0; l < L_LAYERS; l++) W[l] = w[l * VPR + t];

    const float4 b0 = b[0 * VPR + t];
    const float4 b1 = b[1 * VPR + t];
    const float4 b2 = b[2 * VPR + t];
    const float4 b3 = b[3 * VPR + t];

    const float4 B1 = b0;
    const float4 B2 = add4(B1, b1);
    const float4 B3 = add4(B2, b2);
    const float4 Bsum = add4(B3, b3);

    float p1 = dot4(B1, W[1]);
    float p2 = dot4(B2, W[2]);
    float p3 = dot4(B3, W[3]);
    #pragma unroll
    for (int o = 16; o > 0; o >>= 1) {
        p1 += __shfl_down_sync(0xffffffffu, p1, o);
        p2 += __shfl_down_sync(0xffffffffu, p2, o);
        p3 += __shfl_down_sync(0xffffffffu, p3, o);
    }
    if (lane == 0) sbeta[wid] = make_float4(p1, p2, p3, 0.f);
    __syncthreads();

    float beta1 = 0.f, beta2 = 0.f, beta3 = 0.f;
    #pragma unroll
    for (int k = 0; k < 8; k++) {
        const float4 v = sbeta[k];
        beta1 += v.x; beta2 += v.y; beta3 += v.z;
    }

    // ---- row loop: 2 rows in flight, next pair prefetched ----
    const size_t base = (size_t)blockIdx.x * (2 * R_PAIRS * VPR) + t;
    float4 pfA = x[base];
    float4 pfB = x[base + VPR];

    #pragma unroll 1
    for (int p = 0; p < R_PAIRS; p++) {
        const float4 xA = pfA, xB = pfB;
        if (p + 1 < R_PAIRS) {
            pfA = x[base + (size_t)(2 * p + 2) * VPR];
            pfB = x[base + (size_t)(2 * p + 3) * VPR];
        }

        // 4 dots per row, all independent
        float4 pa = make_float4(dot4(xA, W[0]), dot4(xA, W[1]),
                                dot4(xA, W[2]), dot4(xA, W[3]));
        float4 pb = make_float4(dot4(xB, W[0]), dot4(xB, W[1]),
                                dot4(xB, W[2]), dot4(xB, W[3]));

        // single warp-reduction pass over all 8 partials
        #pragma unroll
        for (int o = 16; o > 0; o >>= 1) {
            pa.x += __shfl_down_sync(0xffffffffu, pa.x, o);
            pa.y += __shfl_down_sync(0xffffffffu, pa.y, o);
            pa.z += __shfl_down_sync(0xffffffffu, pa.z, o);
            pa.w += __shfl_down_sync(0xffffffffu, pa.w, o);
            pb.x += __shfl_down_sync(0xffffffffu, pb.x, o);
            pb.y += __shfl_down_sync(0xffffffffu, pb.y, o);
            pb.z += __shfl_down_sync(0xffffffffu, pb.z, o);
            pb.w += __shfl_down_sync(0xffffffffu, pb.w, o);
        }
        const int par = p & 1;
        if (lane == 0) { sred[par][0][wid] = pa; sred[par][1][wid] = pb; }
        __syncthreads();

        float4 tA = make_float4(0.f, 0.f, 0.f, 0.f);
        float4 tB = make_float4(0.f, 0.f, 0.f, 0.f);
        #pragma unroll
        for (int k = 0; k < 8; k++) {
            tA = add4(tA, sred[par][0][k]);
            tB = add4(tB, sred[par][1][k]);
        }

        // scalar recurrence: gamma_4
        float gA = 1.f + tA.x;
        gA += fmaf(gA, tA.y, beta1);
        gA += fmaf(gA, tA.z, beta2);
        gA += fmaf(gA, tA.w, beta3);

        float gB = 1.f + tB.x;
        gB += fmaf(gB, tB.y, beta1);
        gB += fmaf(gB, tB.z, beta2);
        gB += fmaf(gB, tB.w, beta3);

        // out = gamma*x0 + Bsum
        out[base + (size_t)(2 * p) * VPR] =
            make_float4(fmaf(xA.x, gA, Bsum.x), fmaf(xA.y, gA, Bsum.y),
                        fmaf(xA.z, gA, Bsum.z), fmaf(xA.w, gA, Bsum.w));
        out[base + (size_t)(2 * p + 1) * VPR] =
            make_float4(fmaf(xB.x, gB, Bsum.x), fmaf(xB.y, gB, Bsum.y),
                        fmaf(xB.z, gB, Bsum.z), fmaf(xB.w, gB, Bsum.w));
    }
}

extern "C" void kernel_launch(void* const* d_in, const int* in_sizes, int n_in,
                              void* d_out, int out_size) {
    const float4* x = (const float4*)d_in[0];
    const float4* w = (const float4*)d_in[1];
    const float4* b = (const float4*)d_in[2];
    float4* o = (float4*)d_out;
    dcn_cross_kernel<<<B_ROWS / (2 * R_PAIRS), THREADS>>>(x, w, b, o);
}

// round 7
// speedup vs baseline: 1.2364x; 1.1196x over previous
#include <cuda_runtime.h>
#include <cuda_bf16.h>

// DCN cross network, fused, affine-span form (see R5):
//   t_l = x0.w_l (4 independent dots), beta_l = B_l.w_l (row-independent),
//   gamma recurrence, out = gamma4*x0 + Bsum.
// R6: R5 was MIO-bound on reduction plumbing (40 SHFL + 16 LDS per pair).
//  - value-halving warp reduce: 4 dots cost 6 SHFL, results distributed
//    (lane group (lane>>3)&3 holds t_l), 1 STS.32 per warp.
//  - 128 threads per row (CTA = 2 independent halves, 8 elems/thread):
//    halves warps-per-row replication, cross-warp partials 8->4.
//  - per-row: 2 LDG + 6 SHFL + 1 STS + 1 BAR + 4 bcast LDS + 2 STG.

#define B_ROWS   16384
#define L_LAYERS 4
#define THREADS  256
#define HT       128          // threads per half (one row)
#define VPR      256          // float4 vectors per row
#define R_ROWS   4            // rows per half -> 8 rows/CTA, grid = 2048

__device__ __forceinline__ float dot4(const float4 a, const float4 b) {
    return a.x * b.x + a.y * b.y + a.z * b.z + a.w * b.w;
}
__device__ __forceinline__ float4 add4(const float4 a, const float4 b) {
    return make_float4(a.x + b.x, a.y + b.y, a.z + b.z, a.w + b.w);
}

__global__ __launch_bounds__(THREADS, 3)
void dcn_cross_kernel(const float4* __restrict__ x,
                      const float4* __restrict__ w,
                      const float4* __restrict__ b,
                      float4* __restrict__ out) {
    const int t    = threadIdx.x;
    const int lane = t & 31;
    const int h    = t >> 7;           // half id 0/1
    const int ht   = t & (HT - 1);     // 0..127 within half
    const int wh   = (t >> 5) & 3;     // warp within half

    // [parity][half][warp] float4 of (t0,t1,t2,t3); + beta scratch
    __shared__ __align__(16) float4 sred[2][2][4];
    __shared__ __align__(16) float4 sbeta[2][4];

    // ---- W register-resident: 8 elems (2 float4) x 4 layers ----
    float4 W[L_LAYERS][2];
    #pragma unroll
    for (int l = 0; l < L_LAYERS; l++) {
        W[l][0] = w[l * VPR + ht];
        W[l][1] = w[l * VPR + ht + HT];
    }

    // ---- biases: Bsum slice + beta partial dots ----
    float4 Bs0, Bs1;     // running prefix = Bsum at the end
    float p1, p2, p3;
    {
        const float4 b00 = b[0 * VPR + ht], b01 = b[0 * VPR + ht + HT];
        const float4 b10 = b[1 * VPR + ht], b11 = b[1 * VPR + ht + HT];
        const float4 b20 = b[2 * VPR + ht], b21 = b[2 * VPR + ht + HT];
        const float4 b30 = b[3 * VPR + ht], b31 = b[3 * VPR + ht + HT];
        Bs0 = b00; Bs1 = b01;                                  // B1
        p1 = dot4(Bs0, W[1][0]) + dot4(Bs1, W[1][1]);
        Bs0 = add4(Bs0, b10); Bs1 = add4(Bs1, b11);            // B2
        p2 = dot4(Bs0, W[2][0]) + dot4(Bs1, W[2][1]);
        Bs0 = add4(Bs0, b20); Bs1 = add4(Bs1, b21);            // B3
        p3 = dot4(Bs0, W[3][0]) + dot4(Bs1, W[3][1]);
        Bs0 = add4(Bs0, b30); Bs1 = add4(Bs1, b31);            // Bsum
    }
    #pragma unroll
    for (int o = 16; o > 0; o >>= 1) {
        p1 += __shfl_down_sync(0xffffffffu, p1, o);
        p2 += __shfl_down_sync(0xffffffffu, p2, o);
        p3 += __shfl_down_sync(0xffffffffu, p3, o);
    }
    if (lane == 0) sbeta[h][wh] = make_float4(p1, p2, p3, 0.f);
    __syncthreads();
    float beta1, beta2, beta3;
    {
        const float4 v0 = sbeta[h][0], v1 = sbeta[h][1];
        const float4 v2 = sbeta[h][2], v3 = sbeta[h][3];
        beta1 = (v0.x + v1.x) + (v2.x + v3.x);
        beta2 = (v0.y + v1.y) + (v2.y + v3.y);
        beta3 = (v0.z + v1.z) + (v2.z + v3.z);
    }

    // ---- row loop (each half independent; barriers are CTA-uniform) ----
    const size_t rowbase = ((size_t)blockIdx.x * 2 + h) * R_ROWS;
    const float4* xr = x + rowbase * VPR + ht;
    float4* outr     = out + rowbase * VPR + ht;

    float4 pf0 = xr[0], pf1 = xr[HT];          // prefetch row 0

    #pragma unroll 1
    for (int r = 0; r < R_ROWS; r++) {
        const float4 x0 = pf0, x1 = pf1;
        if (r + 1 < R_ROWS) {
            pf0 = xr[(size_t)(r + 1) * VPR];
            pf1 = xr[(size_t)(r + 1) * VPR + HT];
        }

        // 4 layer-dots over this thread's 8 elems
        float V0 = dot4(x0, W[0][0]) + dot4(x1, W[0][1]);
        float V1 = dot4(x0, W[1][0]) + dot4(x1, W[1][1]);
        float V2 = dot4(x0, W[2][0]) + dot4(x1, W[2][1]);
        float V3 = dot4(x0, W[3][0]) + dot4(x1, W[3][1]);

        // value-halving warp reduce: 6 SHFL; lane L ends with full-warp
        // sum of value idx (L>>3)&3
        {
            const bool hi16 = (lane & 16);
            float k0 = hi16 ? V2 : V0, g0 = hi16 ? V0 : V2;
            float k1 = hi16 ? V3 : V1, g1 = hi16 ? V1 : V3;
            V0 = k0 + __shfl_xor_sync(0xffffffffu, g0, 16);
            V1 = k1 + __shfl_xor_sync(0xffffffffu, g1, 16);
            const bool hi8 = (lane & 8);
            float k = hi8 ? V1 : V0, g = hi8 ? V0 : V1;
            V0 = k + __shfl_xor_sync(0xffffffffu, g, 8);
            V0 += __shfl_xor_sync(0xffffffffu, V0, 4);
            V0 += __shfl_xor_sync(0xffffffffu, V0, 2);
            V0 += __shfl_xor_sync(0xffffffffu, V0, 1);
        }

        const int par = r & 1;
        if ((lane & 7) == 0)   // lanes 0,8,16,24 hold t_{lane>>3}
            reinterpret_cast<float*>(&sred[par][h][wh])[lane >> 3] = V0;
        __syncthreads();

        // cross-warp: 4 broadcast LDS.128, components are t0..t3
        const float4 s0 = sred[par][h][0], s1 = sred[par][h][1];
        const float4 s2 = sred[par][h][2], s3 = sred[par][h][3];
        const float t0 = (s0.x + s1.x) + (s2.x + s3.x);
        const float t1 = (s0.y + s1.y) + (s2.y + s3.y);
        const float t2 = (s0.z + s1.z) + (s2.z + s3.z);
        const float t3 = (s0.w + s1.w) + (s2.w + s3.w);

        // gamma recurrence
        float g = 1.f + t0;
        g = fmaf(g, t1, g + beta1);
        g = fmaf(g, t2, g + beta2);
        g = fmaf(g, t3, g + beta3);

        // out = gamma*x0 + Bsum
        outr[(size_t)r * VPR] =
            make_float4(fmaf(x0.x, g, Bs0.x), fmaf(x0.y, g, Bs0.y),
                        fmaf(x0.z, g, Bs0.z), fmaf(x0.w, g, Bs0.w));
        outr[(size_t)r * VPR + HT] =
            make_float4(fmaf(x1.x, g, Bs1.x), fmaf(x1.y, g, Bs1.y),
                        fmaf(x1.z, g, Bs1.z), fmaf(x1.w, g, Bs1.w));
    }
}

extern "C" void kernel_launch(void* const* d_in, const int* in_sizes, int n_in,
                              void* d_out, int out_size) {
    const float4* x = (const float4*)d_in[0];
    const float4* w = (const float4*)d_in[1];
    const float4* b = (const float4*)d_in[2];
    float4* o = (float4*)d_out;
    dcn_cross_kernel<<<B_ROWS / (2 * R_ROWS), THREADS>>>(x, w, b, o);
}

// round 8
// speedup vs baseline: 1.3112x; 1.0605x over previous
#include <cuda_runtime.h>
#include <cuda_bf16.h>

// DCN cross network, fused, affine-span form:
//   t_l = x0.w_l (4 dots, one reduction), beta_l = B_l.w_l (row-indep),
//   gamma recurrence, out = gamma4*x0 + Bsum.
// R7: R6 was latency-bound (nothing >50%). Software pipeline:
//   iter r: dots+reduce+STS for row r | BAR | epilogue (LDS+gamma+STG)
//   for row r-1 from its retained x regs. The reduce chain is consumed
//   one iteration later, so it never gates. 4-deep smem parity buffers.
//   __ldcs/__stcs: x/out are streaming, keep them out of L2's way.

#define B_ROWS   16384
#define L_LAYERS 4
#define THREADS  256
#define HT       128          // threads per half (one row per half)
#define VPR      256          // float4 vectors per row
#define R_ROWS   8            // rows per half -> 16 rows/CTA, grid = 1024

__device__ __forceinline__ float dot4(const float4 a, const float4 b) {
    return a.x * b.x + a.y * b.y + a.z * b.z + a.w * b.w;
}
__device__ __forceinline__ float4 add4(const float4 a, const float4 b) {
    return make_float4(a.x + b.x, a.y + b.y, a.z + b.z, a.w + b.w);
}

__global__ __launch_bounds__(THREADS, 3)
void dcn_cross_kernel(const float4* __restrict__ x,
                      const float4* __restrict__ w,
                      const float4* __restrict__ b,
                      float4* __restrict__ out) {
    const int t    = threadIdx.x;
    const int lane = t & 31;
    const int h    = t >> 7;           // half id 0/1
    const int ht   = t & (HT - 1);     // 0..127 within half
    const int wh   = (t >> 5) & 3;     // warp within half

    __shared__ __align__(16) float4 sred[4][2][4];  // [r&3][half][warp] (t0..t3)
    __shared__ __align__(16) float4 sbeta[2][4];

    // ---- W register-resident: 8 elems (2 float4) x 4 layers ----
    float4 W[L_LAYERS][2];
    #pragma unroll
    for (int l = 0; l < L_LAYERS; l++) {
        W[l][0] = w[l * VPR + ht];
        W[l][1] = w[l * VPR + ht + HT];
    }

    // ---- biases: Bsum slice + beta partial dots ----
    float4 Bs0, Bs1;
    float p1, p2, p3;
    {
        const float4 b00 = b[0 * VPR + ht], b01 = b[0 * VPR + ht + HT];
        const float4 b10 = b[1 * VPR + ht], b11 = b[1 * VPR + ht + HT];
        const float4 b20 = b[2 * VPR + ht], b21 = b[2 * VPR + ht + HT];
        const float4 b30 = b[3 * VPR + ht], b31 = b[3 * VPR + ht + HT];
        Bs0 = b00; Bs1 = b01;                           // B1
        p1 = dot4(Bs0, W[1][0]) + dot4(Bs1, W[1][1]);
        Bs0 = add4(Bs0, b10); Bs1 = add4(Bs1, b11);     // B2
        p2 = dot4(Bs0, W[2][0]) + dot4(Bs1, W[2][1]);
        Bs0 = add4(Bs0, b20); Bs1 = add4(Bs1, b21);     // B3
        p3 = dot4(Bs0, W[3][0]) + dot4(Bs1, W[3][1]);
        Bs0 = add4(Bs0, b30); Bs1 = add4(Bs1, b31);     // Bsum
    }
    #pragma unroll
    for (int o = 16; o > 0; o >>= 1) {
        p1 += __shfl_down_sync(0xffffffffu, p1, o);
        p2 += __shfl_down_sync(0xffffffffu, p2, o);
        p3 += __shfl_down_sync(0xffffffffu, p3, o);
    }
    if (lane == 0) sbeta[h][wh] = make_float4(p1, p2, p3, 0.f);
    __syncthreads();
    float beta1, beta2, beta3;
    {
        const float4 v0 = sbeta[h][0], v1 = sbeta[h][1];
        const float4 v2 = sbeta[h][2], v3 = sbeta[h][3];
        beta1 = (v0.x + v1.x) + (v2.x + v3.x);
        beta2 = (v0.y + v1.y) + (v2.y + v3.y);
        beta3 = (v0.z + v1.z) + (v2.z + v3.z);
    }

    // ---- pipelined row loop ----
    const size_t rowbase = ((size_t)blockIdx.x * 2 + h) * R_ROWS;
    const float4* xr = x + rowbase * VPR + ht;
    float4* outr     = out + rowbase * VPR + ht;

    float4 pf0 = __ldcs(&xr[0]), pf1 = __ldcs(&xr[HT]);   // row 0
    float4 xp0, xp1;                                       // prev row x

    #pragma unroll 1
    for (int r = 0; r < R_ROWS; r++) {
        const float4 x0 = pf0, x1 = pf1;
        if (r + 1 < R_ROWS) {
            pf0 = __ldcs(&xr[(size_t)(r + 1) * VPR]);
            pf1 = __ldcs(&xr[(size_t)(r + 1) * VPR + HT]);
        }

        // 4 layer-dots over this thread's 8 elems
        float V0 = dot4(x0, W[0][0]) + dot4(x1, W[0][1]);
        float V1 = dot4(x0, W[1][0]) + dot4(x1, W[1][1]);
        float V2 = dot4(x0, W[2][0]) + dot4(x1, W[2][1]);
        float V3 = dot4(x0, W[3][0]) + dot4(x1, W[3][1]);

        // value-halving warp reduce: 6 SHFL, result distributed by lane>>3
        {
            const bool hi16 = (lane & 16);
            float k0 = hi16 ? V2 : V0, g0 = hi16 ? V0 : V2;
            float k1 = hi16 ? V3 : V1, g1 = hi16 ? V1 : V3;
            V0 = k0 + __shfl_xor_sync(0xffffffffu, g0, 16);
            V1 = k1 + __shfl_xor_sync(0xffffffffu, g1, 16);
            const bool hi8 = (lane & 8);
            float k = hi8 ? V1 : V0, g = hi8 ? V0 : V1;
            V0 = k + __shfl_xor_sync(0xffffffffu, g, 8);
            V0 += __shfl_xor_sync(0xffffffffu, V0, 4);
            V0 += __shfl_xor_sync(0xffffffffu, V0, 2);
            V0 += __shfl_xor_sync(0xffffffffu, V0, 1);
        }
        if ((lane & 7) == 0)
            reinterpret_cast<float*>(&sred[r & 3][h][wh])[lane >> 3] = V0;
        __syncthreads();

        // deferred epilogue for row r-1 (totals written last iter, safe:
        // buffer (r-1)&3 isn't rewritten until iter r+3)
        if (r > 0) {
            const int pb = (r - 1) & 3;
            const float4 s0 = sred[pb][h][0], s1 = sred[pb][h][1];
            const float4 s2 = sred[pb][h][2], s3 = sred[pb][h][3];
            const float t0 = (s0.x + s1.x) + (s2.x + s3.x);
            const float t1 = (s0.y + s1.y) + (s2.y + s3.y);
            const float t2 = (s0.z + s1.z) + (s2.z + s3.z);
            const float t3 = (s0.w + s1.w) + (s2.w + s3.w);

            float g = 1.f + t0;
            g = fmaf(g, t1, g + beta1);
            g = fmaf(g, t2, g + beta2);
            g = fmaf(g, t3, g + beta3);

            __stcs(&outr[(size_t)(r - 1) * VPR],
                   make_float4(fmaf(xp0.x, g, Bs0.x), fmaf(xp0.y, g, Bs0.y),
                               fmaf(xp0.z, g, Bs0.z), fmaf(xp0.w, g, Bs0.w)));
            __stcs(&outr[(size_t)(r - 1) * VPR + HT],
                   make_float4(fmaf(xp1.x, g, Bs1.x), fmaf(xp1.y, g, Bs1.y),
                               fmaf(xp1.z, g, Bs1.z), fmaf(xp1.w, g, Bs1.w)));
        }
        xp0 = x0; xp1 = x1;
    }

    // tail: epilogue for the last row (its totals were synced in final iter)
    {
        const int pb = (R_ROWS - 1) & 3;
        const float4 s0 = sred[pb][h][0], s1 = sred[pb][h][1];
        const float4 s2 = sred[pb][h][2], s3 = sred[pb][h][3];
        const float t0 = (s0.x + s1.x) + (s2.x + s3.x);
        const float t1 = (s0.y + s1.y) + (s2.y + s3.y);
        const float t2 = (s0.z + s1.z) + (s2.z + s3.z);
        const float t3 = (s0.w + s1.w) + (s2.w + s3.w);

        float g = 1.f + t0;
        g = fmaf(g, t1, g + beta1);
        g = fmaf(g, t2, g + beta2);
        g = fmaf(g, t3, g + beta3);

        __stcs(&outr[(size_t)(R_ROWS - 1) * VPR],
               make_float4(fmaf(xp0.x, g, Bs0.x), fmaf(xp0.y, g, Bs0.y),
                           fmaf(xp0.z, g, Bs0.z), fmaf(xp0.w, g, Bs0.w)));
        __stcs(&outr[(size_t)(R_ROWS - 1) * VPR + HT],
               make_float4(fmaf(xp1.x, g, Bs1.x), fmaf(xp1.y, g, Bs1.y),
                           fmaf(xp1.z, g, Bs1.z), fmaf(xp1.w, g, Bs1.w)));
    }
}

extern "C" void kernel_launch(void* const* d_in, const int* in_sizes, int n_in,
                              void* d_out, int out_size) {
    const float4* x = (const float4*)d_in[0];
    const float4* w = (const float4*)d_in[1];
    const float4* b = (const float4*)d_in[2];
    float4* o = (float4*)d_out;
    dcn_cross_kernel<<<B_ROWS / (2 * R_ROWS), THREADS>>>(x, w, b, o);
}